// round 1
// baseline (speedup 1.0000x reference)
#include <cuda_runtime.h>

#define DIM 1024
#define KV_DIM 768
#define NUM_HEADS 16
#define HEAD_DIM 64
#define BATCH 2
#define LQ 4096
#define LKV 1024

// Scratch (no allocation allowed): 32 + 8 + 8 + 32 = 80 MB
__device__ float g_q[BATCH * LQ * DIM];
__device__ float g_k[BATCH * LKV * DIM];
__device__ float g_v[BATCH * LKV * DIM];
__device__ float g_attn[BATCH * LQ * DIM];

// ---------------------------------------------------------------------------
// Tiled GEMM: C[M,N] = A[M,K] @ W[K,N] + bias[N]
// BM=BN=64, BK=16, 256 threads, 4x4 micro-tile per thread.
// M,N,K all multiples of the tile sizes here (no bounds checks needed).
// ---------------------------------------------------------------------------
__global__ __launch_bounds__(256) void gemm_bias_kernel(
    const float* __restrict__ A, const float* __restrict__ W,
    const float* __restrict__ bias, float* __restrict__ C,
    int M, int N, int K)
{
    const int BM = 64, BN = 64, BK = 16;
    __shared__ float As[BK][BM + 4];  // transposed A tile, padded (row = 272B, 16B-aligned)
    __shared__ float Bs[BK][BN];

    int tid = threadIdx.x;
    int tx = tid & 15;        // 0..15 -> N direction
    int ty = tid >> 4;        // 0..15 -> M direction
    int rowBase = blockIdx.y * BM;
    int colBase = blockIdx.x * BN;

    float acc[4][4] = {};

    for (int kk = 0; kk < K; kk += BK) {
        // Load A tile (64 x 16): each thread one float4
        {
            int r  = tid >> 2;            // 0..63
            int c4 = (tid & 3) * 4;       // 0,4,8,12
            float4 av = *reinterpret_cast<const float4*>(
                &A[(size_t)(rowBase + r) * K + kk + c4]);
            As[c4 + 0][r] = av.x;
            As[c4 + 1][r] = av.y;
            As[c4 + 2][r] = av.z;
            As[c4 + 3][r] = av.w;
        }
        // Load W tile (16 x 64): each thread one float4
        {
            int r  = tid >> 4;            // 0..15
            int c4 = (tid & 15) * 4;      // 0..60
            *reinterpret_cast<float4*>(&Bs[r][c4]) =
                *reinterpret_cast<const float4*>(
                    &W[(size_t)(kk + r) * N + colBase + c4]);
        }
        __syncthreads();

        #pragma unroll
        for (int k = 0; k < BK; k++) {
            float4 a4 = *reinterpret_cast<const float4*>(&As[k][ty * 4]);
            float4 b4 = *reinterpret_cast<const float4*>(&Bs[k][tx * 4]);
            float a[4] = {a4.x, a4.y, a4.z, a4.w};
            float b[4] = {b4.x, b4.y, b4.z, b4.w};
            #pragma unroll
            for (int i = 0; i < 4; i++)
                #pragma unroll
                for (int j = 0; j < 4; j++)
                    acc[i][j] += a[i] * b[j];
        }
        __syncthreads();
    }

    #pragma unroll
    for (int i = 0; i < 4; i++) {
        int row = rowBase + ty * 4 + i;
        #pragma unroll
        for (int j = 0; j < 4; j++) {
            int col = colBase + tx * 4 + j;
            C[(size_t)row * N + col] = acc[i][j] + bias[col];
        }
    }
}

// ---------------------------------------------------------------------------
// RMSNorm (over full DIM) + RoPE (per 64-dim head, cos/sin shared by heads).
// One block (256 threads) per row; in-place on t.
// ---------------------------------------------------------------------------
__global__ __launch_bounds__(256) void rmsnorm_rope_kernel(
    float* __restrict__ t, const float* __restrict__ g,
    const float* __restrict__ cs, const float* __restrict__ sn)
{
    int row = blockIdx.x;
    float* p = t + (size_t)row * DIM;

    __shared__ float sh[DIM];
    __shared__ float red[8];

    int tid = threadIdx.x;
    float4 v = *reinterpret_cast<const float4*>(&p[tid * 4]);
    float ss = v.x * v.x + v.y * v.y + v.z * v.z + v.w * v.w;
    #pragma unroll
    for (int o = 16; o; o >>= 1) ss += __shfl_xor_sync(0xFFFFFFFFu, ss, o);
    if ((tid & 31) == 0) red[tid >> 5] = ss;
    __syncthreads();
    if (tid == 0) {
        float tot = 0.f;
        #pragma unroll
        for (int i = 0; i < 8; i++) tot += red[i];
        red[0] = tot;
    }
    __syncthreads();
    float rms = rsqrtf(red[0] * (1.0f / DIM) + 1e-6f);

    // normalized row -> shared (needed because rotate_half reads the partner)
    float4 gv = *reinterpret_cast<const float4*>(&g[tid * 4]);
    sh[tid * 4 + 0] = v.x * rms * gv.x;
    sh[tid * 4 + 1] = v.y * rms * gv.y;
    sh[tid * 4 + 2] = v.z * rms * gv.z;
    sh[tid * 4 + 3] = v.w * rms * gv.w;
    __syncthreads();

    const float* crow = cs + (size_t)row * HEAD_DIM;
    const float* srow = sn + (size_t)row * HEAD_DIM;
    #pragma unroll
    for (int e = 0; e < 4; e++) {
        int i = tid * 4 + e;
        int d = i & (HEAD_DIM - 1);
        float n = sh[i];
        float other = (d < HEAD_DIM / 2) ? -sh[i + HEAD_DIM / 2]
                                         :  sh[i - HEAD_DIM / 2];
        p[i] = n * crow[d] + other * srow[d];
    }
}

// ---------------------------------------------------------------------------
// Flash attention: one thread = one query row; 128 rows / block per (b,h).
// K/V tiled 64 rows at a time in SMEM; online softmax with rare rescale.
// q,k,v layout: (B, L, H, HD) contiguous = (B, L, DIM).
// ---------------------------------------------------------------------------
__global__ __launch_bounds__(128) void attention_kernel(
    const float* __restrict__ q, const float* __restrict__ k,
    const float* __restrict__ v, float* __restrict__ o)
{
    int b = blockIdx.z;
    int h = blockIdx.y;
    int l = blockIdx.x * 128 + threadIdx.x;
    int tid = threadIdx.x;

    __shared__ float Ks[64][HEAD_DIM];
    __shared__ float Vs[64][HEAD_DIM];

    float qr[HEAD_DIM];
    float ov[HEAD_DIM];

    const float* qp = q + (((size_t)(b * LQ + l)) * NUM_HEADS + h) * HEAD_DIM;
    const float scale = 0.125f;  // 64^-0.5
    #pragma unroll
    for (int d4 = 0; d4 < HEAD_DIM / 4; d4++) {
        float4 t = *reinterpret_cast<const float4*>(qp + d4 * 4);
        qr[d4 * 4 + 0] = t.x * scale;
        qr[d4 * 4 + 1] = t.y * scale;
        qr[d4 * 4 + 2] = t.z * scale;
        qr[d4 * 4 + 3] = t.w * scale;
    }
    #pragma unroll
    for (int d = 0; d < HEAD_DIM; d++) ov[d] = 0.f;
    float mi = -1e30f, li = 0.f;

    for (int m0 = 0; m0 < LKV; m0 += 64) {
        __syncthreads();
        // Load 64x64 K and V tiles: 1024 float4 each, 128 threads x 8
        #pragma unroll
        for (int i = 0; i < 8; i++) {
            int idx = tid * 8 + i;
            int m  = idx >> 4;
            int c4 = (idx & 15) * 4;
            size_t goff = (((size_t)(b * LKV + m0 + m)) * NUM_HEADS + h) * HEAD_DIM + c4;
            *reinterpret_cast<float4*>(&Ks[m][c4]) =
                *reinterpret_cast<const float4*>(&k[goff]);
            *reinterpret_cast<float4*>(&Vs[m][c4]) =
                *reinterpret_cast<const float4*>(&v[goff]);
        }
        __syncthreads();

        for (int m = 0; m < 64; m++) {
            const float4* K4 = reinterpret_cast<const float4*>(Ks[m]);
            float s = 0.f;
            #pragma unroll
            for (int d4 = 0; d4 < HEAD_DIM / 4; d4++) {
                float4 kv = K4[d4];
                s += qr[d4 * 4 + 0] * kv.x + qr[d4 * 4 + 1] * kv.y
                   + qr[d4 * 4 + 2] * kv.z + qr[d4 * 4 + 3] * kv.w;
            }
            if (s > mi) {  // rare path: new running max
                float sc = __expf(mi - s);
                li *= sc;
                #pragma unroll
                for (int d = 0; d < HEAD_DIM; d++) ov[d] *= sc;
                mi = s;
            }
            float pexp = __expf(s - mi);
            li += pexp;
            const float4* V4 = reinterpret_cast<const float4*>(Vs[m]);
            #pragma unroll
            for (int d4 = 0; d4 < HEAD_DIM / 4; d4++) {
                float4 vv = V4[d4];
                ov[d4 * 4 + 0] += pexp * vv.x;
                ov[d4 * 4 + 1] += pexp * vv.y;
                ov[d4 * 4 + 2] += pexp * vv.z;
                ov[d4 * 4 + 3] += pexp * vv.w;
            }
        }
    }

    float inv = 1.0f / li;
    float* op = o + (((size_t)(b * LQ + l)) * NUM_HEADS + h) * HEAD_DIM;
    #pragma unroll
    for (int d4 = 0; d4 < HEAD_DIM / 4; d4++) {
        float4 t;
        t.x = ov[d4 * 4 + 0] * inv;
        t.y = ov[d4 * 4 + 1] * inv;
        t.z = ov[d4 * 4 + 2] * inv;
        t.w = ov[d4 * 4 + 3] * inv;
        *reinterpret_cast<float4*>(op + d4 * 4) = t;
    }
}

// ---------------------------------------------------------------------------
extern "C" void kernel_launch(void* const* d_in, const int* in_sizes, int n_in,
                              void* d_out, int out_size)
{
    const float* x     = (const float*)d_in[0];
    const float* y     = (const float*)d_in[1];
    const float* x_cos = (const float*)d_in[2];
    const float* x_sin = (const float*)d_in[3];
    const float* y_cos = (const float*)d_in[4];
    const float* y_sin = (const float*)d_in[5];
    const float* Wq    = (const float*)d_in[6];
    const float* bq    = (const float*)d_in[7];
    const float* Wk    = (const float*)d_in[8];
    const float* bk    = (const float*)d_in[9];
    const float* Wv    = (const float*)d_in[10];
    const float* bv    = (const float*)d_in[11];
    const float* Wo    = (const float*)d_in[12];
    const float* bo    = (const float*)d_in[13];
    const float* gq    = (const float*)d_in[14];
    const float* gk    = (const float*)d_in[15];
    float* out = (float*)d_out;

    float *q, *k, *v, *attn;
    cudaGetSymbolAddress((void**)&q,    g_q);
    cudaGetSymbolAddress((void**)&k,    g_k);
    cudaGetSymbolAddress((void**)&v,    g_v);
    cudaGetSymbolAddress((void**)&attn, g_attn);

    const int Mq = BATCH * LQ;    // 8192
    const int Mk = BATCH * LKV;   // 2048

    // Projections
    gemm_bias_kernel<<<dim3(DIM / 64, Mq / 64), 256>>>(x, Wq, bq, q, Mq, DIM, DIM);
    gemm_bias_kernel<<<dim3(DIM / 64, Mk / 64), 256>>>(y, Wk, bk, k, Mk, DIM, KV_DIM);
    gemm_bias_kernel<<<dim3(DIM / 64, Mk / 64), 256>>>(y, Wv, bv, v, Mk, DIM, KV_DIM);

    // Norm + RoPE (in place)
    rmsnorm_rope_kernel<<<Mq, 256>>>(q, gq, x_cos, x_sin);
    rmsnorm_rope_kernel<<<Mk, 256>>>(k, gk, y_cos, y_sin);

    // Attention
    attention_kernel<<<dim3(LQ / 128, NUM_HEADS, BATCH), 128>>>(q, k, v, attn);

    // Output projection
    gemm_bias_kernel<<<dim3(DIM / 64, Mq / 64), 256>>>(attn, Wo, bo, out, Mq, DIM, DIM);
}